// round 3
// baseline (speedup 1.0000x reference)
#include <cuda_runtime.h>
#include <cuda_bf16.h>
#include <cstdint>

// Problem constants
#define NMAX   1000000
#define CCLS   100
#define NBINS  20
#define NBOUND 19          // NBINS-1 boundaries
#define LCAP   2048        // per-boundary gather list capacity

// -------- scratch (static __device__ — no allocations allowed) --------
__device__ unsigned int      g_confBits[NMAX];
__device__ unsigned char     g_acc[NMAX];
__device__ unsigned int      g_hist1[4096];
__device__ unsigned int      g_hist2[NBOUND * 8192];
__device__ unsigned char     g_lut1[4096];
__device__ unsigned int      g_bucket1[NBOUND];
__device__ unsigned int      g_rr1[NBOUND];
__device__ int               g_slotOfBoundary[NBOUND];
__device__ int               g_nslots1;
__device__ unsigned int      g_pref25[NBOUND];
__device__ unsigned int      g_rr2[NBOUND];
__device__ int               g_pslot[NBOUND];
__device__ int               g_nslots3;
__device__ unsigned int      g_listCnt[NBOUND];
__device__ unsigned int      g_list[NBOUND * LCAP];
__device__ unsigned long long g_thresh[NBOUND];
__device__ float             g_binConf[NBINS];
__device__ unsigned int      g_binAcc[NBINS];

// -------- Z: zero scratch (graph replays must be idempotent) --------
__global__ void kZero() {
    int i = blockIdx.x * blockDim.x + threadIdx.x;
    if (i < NBOUND * 8192) g_hist2[i] = 0u;
    if (i < 4096) { g_hist1[i] = 0u; g_lut1[i] = 0xFFu; }
    if (i < NBINS) { g_binConf[i] = 0.f; g_binAcc[i] = 0u; }
    if (i < NBOUND) { g_listCnt[i] = 0u; g_thresh[i] = 0ULL; }
}

// -------- A: fused softmax-conf / argmax-acc / coarse histogram --------
// One warp per row: 25 lanes x float4 = 100 logits, coalesced 400B row read.
// conf = max softmax = 1 / sum_i exp(x_i - max)   (algebraically identical to
// the reference's jnp.max(softmax)). Precise expf keeps ordering faithful.
__global__ void kConf(const float* __restrict__ logits,
                      const int* __restrict__ labels, int N) {
    __shared__ unsigned int sh[4096];
    int t = threadIdx.x;
    for (int k = t; k < 4096; k += blockDim.x) sh[k] = 0u;
    __syncthreads();

    int lane   = t & 31;
    int warp   = blockIdx.x * (blockDim.x >> 5) + (t >> 5);
    int nwarps = gridDim.x * (blockDim.x >> 5);
    bool valid = lane < 25;

    for (int row = warp; row < N; row += nwarps) {
        const float4* rp = reinterpret_cast<const float4*>(logits + (size_t)row * CCLS);
        float4 v = make_float4(0.f, 0.f, 0.f, 0.f);
        if (valid) v = __ldg(rp + lane);

        // per-lane max + first-index argmax (matches jnp.argmax tie-break)
        float m = -3.4e38f; int mi = 0x7FFFFFFF;
        if (valid) {
            m = v.x; mi = lane * 4;
            if (v.y > m) { m = v.y; mi = lane * 4 + 1; }
            if (v.z > m) { m = v.z; mi = lane * 4 + 2; }
            if (v.w > m) { m = v.w; mi = lane * 4 + 3; }
        }
        #pragma unroll
        for (int off = 16; off; off >>= 1) {
            float om = __shfl_xor_sync(0xffffffffu, m, off);
            int  omi = __shfl_xor_sync(0xffffffffu, mi, off);
            if (om > m || (om == m && omi < mi)) { m = om; mi = omi; }
        }
        float s = 0.f;
        if (valid)
            s = expf(v.x - m) + expf(v.y - m) + expf(v.z - m) + expf(v.w - m);
        #pragma unroll
        for (int off = 16; off; off >>= 1)
            s += __shfl_xor_sync(0xffffffffu, s, off);

        if (lane == 0) {
            float conf = 1.0f / s;                      // in (0,1]: bits order-monotonic
            unsigned int kb = __float_as_uint(conf);
            g_confBits[row] = kb;
            g_acc[row] = (labels[row] == mi) ? 1 : 0;
            atomicAdd(&sh[kb >> 20], 1u);               // coarse 12-bit histogram
        }
    }
    __syncthreads();
    for (int k = t; k < 4096; k += blockDim.x) {
        unsigned int v = sh[k];
        if (v) atomicAdd(&g_hist1[k], v);
    }
}

// -------- B: level-1 prefix scan + boundary bucket resolution --------
__global__ void kScan1(int window) {
    __shared__ unsigned int P[4096];
    __shared__ unsigned int part[256];
    int t = threadIdx.x;
    unsigned int sum = 0;
    int base = t * 16;
    #pragma unroll
    for (int k = 0; k < 16; k++) sum += g_hist1[base + k];
    part[t] = sum; __syncthreads();
    unsigned int mys = sum;
    for (int off = 1; off < 256; off <<= 1) {
        unsigned int v = (t >= off) ? part[t - off] : 0u;
        __syncthreads(); part[t] += v; __syncthreads();
    }
    unsigned int run = part[t] - mys;                  // exclusive prefix
    #pragma unroll
    for (int k = 0; k < 16; k++) { P[base + k] = run; run += g_hist1[base + k]; }
    __syncthreads();
    if (t == 0) {
        int ns = 0, prevb = -1;
        for (int i = 0; i < NBOUND; i++) {
            unsigned int r = (unsigned int)((i + 1) * window);  // rank of boundary elem
            int lo = 0, hi = 4095;
            while (lo < hi) { int mid = (lo + hi + 1) >> 1; if (P[mid] <= r) lo = mid; else hi = mid - 1; }
            g_bucket1[i] = (unsigned int)lo;
            g_rr1[i] = r - P[lo];                      // residual rank within bucket
            if (lo != prevb) { g_lut1[lo] = (unsigned char)ns; ns++; prevb = lo; }
            g_slotOfBoundary[i] = ns - 1;
        }
        g_nslots1 = ns;
    }
}

// -------- C: level-2 histogram (13 mid bits) for boundary buckets --------
__global__ void kHist2(int N) {
    int stride = gridDim.x * blockDim.x;
    for (int i = blockIdx.x * blockDim.x + threadIdx.x; i < N; i += stride) {
        unsigned int k = g_confBits[i];
        unsigned int s = g_lut1[k >> 20];
        if (s != 0xFFu)
            atomicAdd(&g_hist2[s * 8192 + ((k >> 7) & 8191u)], 1u);
    }
}

// -------- D: level-2 scan + boundary sub-bucket resolution --------
__global__ void kScan2() {
    __shared__ unsigned int P[8192];
    __shared__ unsigned int part[256];
    int t = threadIdx.x;
    int ns1 = g_nslots1;
    int ns3 = 0;                       // thread 0 only
    unsigned int prevPref = 0xFFFFFFFFu;
    for (int s = 0; s < ns1; s++) {
        const unsigned int* h = &g_hist2[s * 8192];
        unsigned int sum = 0;
        int base = t * 32;
        for (int k = 0; k < 32; k++) sum += h[base + k];
        part[t] = sum; __syncthreads();
        unsigned int mys = sum;
        for (int off = 1; off < 256; off <<= 1) {
            unsigned int v = (t >= off) ? part[t - off] : 0u;
            __syncthreads(); part[t] += v; __syncthreads();
        }
        unsigned int run = part[t] - mys;
        for (int k = 0; k < 32; k++) { P[base + k] = run; run += h[base + k]; }
        __syncthreads();
        if (t == 0) {
            for (int i = 0; i < NBOUND; i++) {
                if (g_slotOfBoundary[i] != s) continue;
                unsigned int rr = g_rr1[i];
                int lo = 0, hi = 8191;
                while (lo < hi) { int mid = (lo + hi + 1) >> 1; if (P[mid] <= rr) lo = mid; else hi = mid - 1; }
                g_rr2[i] = rr - P[lo];
                unsigned int pref = (g_bucket1[i] << 13) | (unsigned int)lo;  // 25-bit prefix
                if (pref != prevPref) { g_pref25[ns3] = pref; ns3++; prevPref = pref; }
                g_pslot[i] = ns3 - 1;
            }
            g_nslots3 = ns3;
        }
        __syncthreads();
    }
}

// -------- E: gather elements sharing a boundary 25-bit prefix --------
// Expected list sizes: O(10-100) of 1M samples per prefix; LCAP=2048 is ample.
__global__ void kGather(int N) {
    int ns = g_nslots3;
    unsigned int pf[NBOUND];
    #pragma unroll
    for (int j = 0; j < NBOUND; j++)
        pf[j] = (j < ns) ? g_pref25[j] : 0xFFFFFFFFu;  // 25-bit p never matches sentinel
    int stride = gridDim.x * blockDim.x;
    for (int i = blockIdx.x * blockDim.x + threadIdx.x; i < N; i += stride) {
        unsigned int k = g_confBits[i];
        unsigned int p = k >> 7;
        #pragma unroll
        for (int j = 0; j < NBOUND; j++) {
            if (p == pf[j]) {
                unsigned int pos = atomicAdd(&g_listCnt[j], 1u);
                if (pos < LCAP)
                    g_list[j * LCAP + pos] = ((k & 127u) << 20) | (unsigned int)i;
            }
        }
    }
}

// -------- F: exact rank select inside each boundary list --------
// Composite sub-key (low7 conf bits, sample index): unique per element, and its
// uint order == full (confBits, index) stable-sort order within the prefix.
__global__ void kSelect() {
    int w = threadIdx.x >> 5, lane = threadIdx.x & 31;
    if (w >= NBOUND) return;
    int p = g_pslot[w];
    unsigned int n = g_listCnt[p]; if (n > LCAP) n = LCAP;
    unsigned int rr2 = g_rr2[w];
    const unsigned int* L = &g_list[p * LCAP];
    for (unsigned int j = lane; j < n; j += 32) {
        unsigned int e = L[j];
        unsigned int rank = 0;
        for (unsigned int k = 0; k < n; k++) rank += (L[k] < e) ? 1u : 0u;
        if (rank == rr2) {
            unsigned int fullkey = (g_pref25[p] << 7) | (e >> 20);
            unsigned long long comp =
                ((unsigned long long)fullkey << 20) | (unsigned long long)(e & 0xFFFFFu);
            g_thresh[w] = comp;   // exact composite key of boundary element
        }
    }
}

// -------- G: per-bin accumulation of conf sums + acc counts --------
// bin(x) = #{ thresholds <= comp(x) }  ==  floor(stable_rank / window)
__global__ void kBin(int N) {
    __shared__ unsigned long long T[NBOUND];
    __shared__ float sconf[NBINS];
    __shared__ unsigned int sacc[NBINS];
    int t = threadIdx.x;
    if (t < NBOUND) T[t] = g_thresh[t];
    if (t < NBINS) { sconf[t] = 0.f; sacc[t] = 0u; }
    __syncthreads();
    int stride = gridDim.x * blockDim.x;
    for (int i = blockIdx.x * blockDim.x + t; i < N; i += stride) {
        unsigned int k = g_confBits[i];
        unsigned long long comp = ((unsigned long long)k << 20) | (unsigned long long)i;
        int bin = 0;
        #pragma unroll
        for (int j = 0; j < NBOUND; j++) bin += (comp >= T[j]) ? 1 : 0;
        atomicAdd(&sconf[bin], __uint_as_float(k));
        atomicAdd(&sacc[bin], (unsigned int)g_acc[i]);
    }
    __syncthreads();
    if (t < NBINS) {
        if (sconf[t] != 0.f) atomicAdd(&g_binConf[t], sconf[t]);
        if (sacc[t]) atomicAdd(&g_binAcc[t], sacc[t]);
    }
}

// -------- H: finalize ECE + acc_bins (out = [ece, acc_bins[0..19]]) --------
__global__ void kFinal(float* __restrict__ out, int out_size, int window, int N) {
    int t = threadIdx.x;
    float accm = 0.f, d = 0.f;
    float inv = 1.0f / (float)window;
    if (t < NBINS) {
        float confm = g_binConf[t] * inv;
        accm = (float)g_binAcc[t] * inv;
        d = fabsf(confm - accm);
    }
    #pragma unroll
    for (int off = 16; off; off >>= 1) d += __shfl_xor_sync(0xffffffffu, d, off);
    float scale = (float)window / (float)N;
    if (t == 0 && out_size > 0) out[0] = d * scale;
    if (t < NBINS && 1 + t < out_size) out[1 + t] = accm;
}

extern "C" void kernel_launch(void* const* d_in, const int* in_sizes, int n_in,
                              void* d_out, int out_size) {
    const float* logits = (const float*)d_in[0];
    const int*   labels = (const int*)d_in[1];
    float* out = (float*)d_out;

    int N = in_sizes[1];          // number of samples (labels count)
    if (N > NMAX) N = NMAX;
    int window = N / NBINS;

    kZero<<<(NBOUND * 8192 + 255) / 256, 256>>>();
    kConf<<<1184, 256>>>(logits, labels, N);
    kScan1<<<1, 256>>>(window);
    kHist2<<<296, 256>>>(N);
    kScan2<<<1, 256>>>();
    kGather<<<296, 256>>>(N);
    kSelect<<<1, NBOUND * 32>>>();
    kBin<<<296, 256>>>(N);
    kFinal<<<1, 32>>>(out, out_size, window, N);
}

// round 17
// speedup vs baseline: 1.6008x; 1.6008x over previous
#include <cuda_runtime.h>
#include <cuda_bf16.h>
#include <cstdint>

// Problem constants
#define NMAX   1000000
#define CCLS   100
#define NBINS  20
#define NBOUND 19          // NBINS-1 boundaries
#define LCAP   2048        // per-boundary gather list capacity

// -------- scratch (static __device__ — no allocations allowed) --------
__device__ __align__(16) unsigned int  g_confBits[NMAX];
__device__ __align__(16) unsigned char g_acc[NMAX];
__device__ unsigned int      g_hist1[4096];
__device__ unsigned int      g_hist2[NBOUND * 8192];
__device__ unsigned char     g_lut1[4096];
__device__ unsigned int      g_bucket1[NBOUND];
__device__ unsigned int      g_rr1[NBOUND];
__device__ int               g_slotOfBoundary[NBOUND];
__device__ unsigned int      g_pref25[NBOUND];
__device__ unsigned int      g_rr2[NBOUND];
__device__ unsigned int      g_listCnt[NBOUND];
__device__ unsigned int      g_list[NBOUND * LCAP];
__device__ unsigned long long g_thresh[NBOUND];
__device__ unsigned long long g_binPacked[NBINS];   // (confFix28 sum << 20) | acc count

// -------- Z: zero scratch (graph replays must be idempotent) --------
__global__ void kZero() {
    int i = blockIdx.x * blockDim.x + threadIdx.x;
    if (i < NBOUND * 8192) g_hist2[i] = 0u;
    if (i < 4096) { g_hist1[i] = 0u; g_lut1[i] = 0xFFu; }
    if (i < NBINS) g_binPacked[i] = 0ULL;
    if (i < NBOUND) { g_listCnt[i] = 0u; g_thresh[i] = 0ULL; }
}

// -------- A: fused softmax-conf / argmax-acc / coarse histogram --------
// One warp per row (25 lanes x float4 = 400B coalesced read). Issue-optimized:
// REDUX for argmax (bit-exact, first-index tie-break), __expf (3 instrs/call),
// prefetched next row for MLP=2.
__global__ void __launch_bounds__(256) kConf(const float* __restrict__ logits,
                                             const int* __restrict__ labels, int N) {
    __shared__ unsigned int sh[4096];
    int t = threadIdx.x;
    for (int k = t; k < 4096; k += 256) sh[k] = 0u;
    __syncthreads();

    int lane   = t & 31;
    int warp   = blockIdx.x * 8 + (t >> 5);
    int nwarps = gridDim.x * 8;
    bool valid = lane < 25;

    int row = warp;
    float4 v = make_float4(0.f, 0.f, 0.f, 0.f);
    if (row < N && valid)
        v = __ldg(reinterpret_cast<const float4*>(logits + (size_t)row * CCLS) + lane);

    for (; row < N; row += nwarps) {
        int nrow = row + nwarps;
        float4 vn = make_float4(0.f, 0.f, 0.f, 0.f);
        if (nrow < N && valid)
            vn = __ldg(reinterpret_cast<const float4*>(logits + (size_t)nrow * CCLS) + lane);

        // per-lane max + first-index argmax
        float m = v.x; int mi = lane * 4;
        if (valid) {
            if (v.y > m) { m = v.y; mi = lane * 4 + 1; }
            if (v.z > m) { m = v.z; mi = lane * 4 + 2; }
            if (v.w > m) { m = v.w; mi = lane * 4 + 3; }
        }
        // order-monotonic uint transform; invalid lanes contribute identity 0
        unsigned b  = __float_as_uint(m);
        unsigned ou = valid ? (b ^ (unsigned)(((int)b >> 31) | 0x80000000)) : 0u;
        unsigned omax = __reduce_max_sync(0xffffffffu, ou);
        unsigned cand = (ou == omax) ? (unsigned)mi : 0xffffffffu;
        unsigned gmi  = __reduce_min_sync(0xffffffffu, cand);   // first-index tie-break
        unsigned mb   = (omax & 0x80000000u) ? (omax ^ 0x80000000u) : ~omax;
        float gm = __uint_as_float(mb);

        float s = 0.f;
        if (valid)
            s = __expf(v.x - gm) + __expf(v.y - gm) + __expf(v.z - gm) + __expf(v.w - gm);
        #pragma unroll
        for (int off = 16; off; off >>= 1)
            s += __shfl_xor_sync(0xffffffffu, s, off);

        if (lane == 0) {
            float conf = 1.0f / s;                       // (0,1]: bits order-monotonic
            unsigned kb = __float_as_uint(conf);
            g_confBits[row] = kb;
            g_acc[row] = (labels[row] == (int)gmi) ? 1 : 0;
            atomicAdd(&sh[kb >> 20], 1u);                // coarse 12-bit histogram
        }
        v = vn;
    }
    __syncthreads();
    for (int k = t; k < 4096; k += 256) {
        unsigned vv = sh[k];
        if (vv) atomicAdd(&g_hist1[k], vv);
    }
}

// -------- B: level-1 prefix scan + boundary bucket resolution --------
__global__ void kScan1(int window) {
    __shared__ unsigned int P[4096];
    __shared__ unsigned int part[256];
    int t = threadIdx.x;
    unsigned int sum = 0;
    int base = t * 16;
    #pragma unroll
    for (int k = 0; k < 16; k++) sum += g_hist1[base + k];
    part[t] = sum; __syncthreads();
    unsigned int mys = sum;
    for (int off = 1; off < 256; off <<= 1) {
        unsigned int vv = (t >= off) ? part[t - off] : 0u;
        __syncthreads(); part[t] += vv; __syncthreads();
    }
    unsigned int run = part[t] - mys;                  // exclusive prefix
    #pragma unroll
    for (int k = 0; k < 16; k++) { P[base + k] = run; run += g_hist1[base + k]; }
    __syncthreads();
    if (t == 0) {
        int ns = 0, prevb = -1;
        for (int i = 0; i < NBOUND; i++) {
            unsigned int r = (unsigned int)((i + 1) * window);  // rank of boundary elem
            int lo = 0, hi = 4095;
            while (lo < hi) { int mid = (lo + hi + 1) >> 1; if (P[mid] <= r) lo = mid; else hi = mid - 1; }
            g_bucket1[i] = (unsigned int)lo;
            g_rr1[i] = r - P[lo];                      // residual rank within bucket
            if (lo != prevb) { g_lut1[lo] = (unsigned char)ns; ns++; prevb = lo; }
            g_slotOfBoundary[i] = ns - 1;
        }
    }
}

// -------- C: level-2 histogram (13 mid bits) for boundary buckets --------
__global__ void kHist2(int N) {
    int stride = gridDim.x * blockDim.x;
    int N4 = N >> 2;
    const uint4* cb = reinterpret_cast<const uint4*>(g_confBits);
    for (int i = blockIdx.x * blockDim.x + threadIdx.x; i < N4; i += stride) {
        uint4 q = cb[i];
        unsigned s;
        s = g_lut1[q.x >> 20]; if (s != 0xFFu) atomicAdd(&g_hist2[s * 8192 + ((q.x >> 7) & 8191u)], 1u);
        s = g_lut1[q.y >> 20]; if (s != 0xFFu) atomicAdd(&g_hist2[s * 8192 + ((q.y >> 7) & 8191u)], 1u);
        s = g_lut1[q.z >> 20]; if (s != 0xFFu) atomicAdd(&g_hist2[s * 8192 + ((q.z >> 7) & 8191u)], 1u);
        s = g_lut1[q.w >> 20]; if (s != 0xFFu) atomicAdd(&g_hist2[s * 8192 + ((q.w >> 7) & 8191u)], 1u);
    }
    if (blockIdx.x == 0 && threadIdx.x < (unsigned)(N & 3)) {   // tail
        int i = (N & ~3) + threadIdx.x;
        unsigned k = g_confBits[i];
        unsigned s = g_lut1[k >> 20];
        if (s != 0xFFu) atomicAdd(&g_hist2[s * 8192 + ((k >> 7) & 8191u)], 1u);
    }
}

// -------- D: level-2 scan — ONE BLOCK PER BOUNDARY (parallel) --------
__global__ void kScan2() {
    __shared__ unsigned int P[8192];
    __shared__ unsigned int part[256];
    int t = threadIdx.x;
    int j = blockIdx.x;                     // boundary id
    int s = g_slotOfBoundary[j];
    const unsigned int* h = &g_hist2[s * 8192];
    unsigned int sum = 0;
    int base = t * 32;
    #pragma unroll
    for (int k = 0; k < 32; k++) sum += h[base + k];
    part[t] = sum; __syncthreads();
    unsigned int mys = sum;
    for (int off = 1; off < 256; off <<= 1) {
        unsigned int vv = (t >= off) ? part[t - off] : 0u;
        __syncthreads(); part[t] += vv; __syncthreads();
    }
    unsigned int run = part[t] - mys;
    #pragma unroll
    for (int k = 0; k < 32; k++) { P[base + k] = run; run += h[base + k]; }
    __syncthreads();
    if (t == 0) {
        unsigned int rr = g_rr1[j];
        int lo = 0, hi = 8191;
        while (lo < hi) { int mid = (lo + hi + 1) >> 1; if (P[mid] <= rr) lo = mid; else hi = mid - 1; }
        g_rr2[j] = rr - P[lo];
        g_pref25[j] = (g_bucket1[j] << 13) | (unsigned int)lo;   // 25-bit prefix
    }
}

// -------- E: gather elements sharing a boundary 25-bit prefix --------
// Per-boundary lists (duplicate prefixes just duplicate tiny lists).
__global__ void kGather(int N) {
    unsigned int pf[NBOUND];
    #pragma unroll
    for (int j = 0; j < NBOUND; j++) pf[j] = g_pref25[j];
    int stride = gridDim.x * blockDim.x;
    int N4 = N >> 2;
    const uint4* cb = reinterpret_cast<const uint4*>(g_confBits);
    for (int i = blockIdx.x * blockDim.x + threadIdx.x; i < N4; i += stride) {
        uint4 q = cb[i];
        unsigned ks[4] = { q.x, q.y, q.z, q.w };
        #pragma unroll
        for (int c = 0; c < 4; c++) {
            unsigned k = ks[c];
            unsigned p = k >> 7;
            unsigned idx = (unsigned)(i * 4 + c);
            #pragma unroll
            for (int j = 0; j < NBOUND; j++) {
                if (p == pf[j]) {
                    unsigned pos = atomicAdd(&g_listCnt[j], 1u);
                    if (pos < LCAP)
                        g_list[j * LCAP + pos] = ((k & 127u) << 20) | idx;
                }
            }
        }
    }
    if (blockIdx.x == 0 && threadIdx.x < (unsigned)(N & 3)) {   // tail
        int i = (N & ~3) + threadIdx.x;
        unsigned k = g_confBits[i];
        unsigned p = k >> 7;
        for (int j = 0; j < NBOUND; j++) {
            if (p == pf[j]) {
                unsigned pos = atomicAdd(&g_listCnt[j], 1u);
                if (pos < LCAP) g_list[j * LCAP + pos] = ((k & 127u) << 20) | (unsigned)i;
            }
        }
    }
}

// -------- F: exact rank select inside each boundary list --------
// Sub-key (low7 conf bits, index): order == stable (confBits, index) order.
__global__ void kSelect() {
    int w = threadIdx.x >> 5, lane = threadIdx.x & 31;
    if (w >= NBOUND) return;
    unsigned int n = g_listCnt[w]; if (n > LCAP) n = LCAP;
    unsigned int rr2 = g_rr2[w];
    const unsigned int* L = &g_list[w * LCAP];
    for (unsigned int j = lane; j < n; j += 32) {
        unsigned int e = L[j];
        unsigned int rank = 0;
        for (unsigned int k = 0; k < n; k++) rank += (L[k] < e) ? 1u : 0u;
        if (rank == rr2) {
            unsigned int fullkey = (g_pref25[w] << 7) | (e >> 20);
            g_thresh[w] = ((unsigned long long)fullkey << 20) |
                          (unsigned long long)(e & 0xFFFFFu);
        }
    }
}

// -------- G: per-bin accumulation, packed u64 (confFix28<<20 | acc) --------
// bin(x) = #{ thresholds <= comp(x) } == floor(stable_rank / window).
// 50000 * 2^28 fixed-point sums fit: 50000*2^48 < 2^64; acc <= 50000 < 2^20.
__device__ __forceinline__ void accum1(unsigned long long* bins,
                                       const unsigned long long* T,
                                       unsigned k, unsigned a, unsigned idx) {
    unsigned long long comp = ((unsigned long long)k << 20) | (unsigned long long)idx;
    int bin = 0;
    #pragma unroll
    for (int j = 0; j < NBOUND; j++) bin += (comp >= T[j]) ? 1 : 0;
    unsigned sfix = __float2uint_rn(__uint_as_float(k) * 268435456.0f);  // conf * 2^28
    atomicAdd(&bins[bin], ((unsigned long long)sfix << 20) | (unsigned long long)a);
}

__global__ void kBin(int N) {
    __shared__ unsigned long long T[NBOUND];
    __shared__ unsigned long long bins[NBINS];
    int t = threadIdx.x;
    if (t < NBOUND) T[t] = g_thresh[t];
    if (t < NBINS) bins[t] = 0ULL;
    __syncthreads();
    int stride = gridDim.x * blockDim.x;
    int N4 = N >> 2;
    const uint4*  cb = reinterpret_cast<const uint4*>(g_confBits);
    const uchar4* ac = reinterpret_cast<const uchar4*>(g_acc);
    for (int i = blockIdx.x * blockDim.x + t; i < N4; i += stride) {
        uint4 q = cb[i]; uchar4 a = ac[i];
        unsigned idx0 = (unsigned)(i * 4);
        accum1(bins, T, q.x, a.x, idx0);
        accum1(bins, T, q.y, a.y, idx0 + 1);
        accum1(bins, T, q.z, a.z, idx0 + 2);
        accum1(bins, T, q.w, a.w, idx0 + 3);
    }
    if (blockIdx.x == 0 && t < (unsigned)(N & 3)) {            // tail
        int i = (N & ~3) + t;
        accum1(bins, T, g_confBits[i], g_acc[i], (unsigned)i);
    }
    __syncthreads();
    if (t < NBINS && bins[t] != 0ULL) atomicAdd(&g_binPacked[t], bins[t]);
}

// -------- H: finalize ECE + acc_bins (out = [ece, acc_bins[0..19]]) --------
__global__ void kFinal(float* __restrict__ out, int out_size, int window, int N) {
    int t = threadIdx.x;
    float accm = 0.f, d = 0.f;
    float inv = 1.0f / (float)window;
    if (t < NBINS) {
        unsigned long long p = g_binPacked[t];
        double confsum = (double)(p >> 20) * (1.0 / 268435456.0);
        float confm = (float)confsum * inv;
        accm = (float)(unsigned)(p & 0xFFFFFu) * inv;
        d = fabsf(confm - accm);
    }
    #pragma unroll
    for (int off = 16; off; off >>= 1) d += __shfl_xor_sync(0xffffffffu, d, off);
    float scale = (float)window / (float)N;
    if (t == 0 && out_size > 0) out[0] = d * scale;
    if (t < NBINS && 1 + t < out_size) out[1 + t] = accm;
}

extern "C" void kernel_launch(void* const* d_in, const int* in_sizes, int n_in,
                              void* d_out, int out_size) {
    const float* logits = (const float*)d_in[0];
    const int*   labels = (const int*)d_in[1];
    float* out = (float*)d_out;

    int N = in_sizes[1];          // number of samples (labels count)
    if (N > NMAX) N = NMAX;
    int window = N / NBINS;

    kZero<<<(NBOUND * 8192 + 255) / 256, 256>>>();
    kConf<<<1184, 256>>>(logits, labels, N);
    kScan1<<<1, 256>>>(window);
    kHist2<<<592, 256>>>(N);
    kScan2<<<NBOUND, 256>>>();
    kGather<<<592, 256>>>(N);
    kSelect<<<1, NBOUND * 32>>>();
    kBin<<<592, 256>>>(N);
    kFinal<<<1, 32>>>(out, out_size, window, N);
}